// round 9
// baseline (speedup 1.0000x reference)
#include <cuda_runtime.h>

#define CIN  3
#define COUT 16
#define OD   62
#define OH   62
#define OW   62

typedef unsigned long long ull;

__device__ __forceinline__ void fma2(ull& acc, ull x, ull w) {
    asm("fma.rn.f32x2 %0, %1, %2, %0;" : "+l"(acc) : "l"(x), "l"(w));
}
__device__ __forceinline__ ull rep2(float a) {
    ull r;
    asm("mov.b64 %0, {%1, %1};" : "=l"(r) : "f"(a));
    return r;
}
__device__ __forceinline__ float2 unpk(ull v) {
    float2 r;
    asm("mov.b64 {%0, %1}, %2;" : "=f"(r.x), "=f"(r.y) : "l"(v));
    return r;
}
// {high32(a), low32(b)} -> packed pair {a.y, b.x}
__device__ __forceinline__ ull mid2(ull a, ull b) {
    ull r;
    const unsigned ahi = (unsigned)(a >> 32);
    const unsigned blo = (unsigned)b;
    asm("mov.b64 %0, {%1, %2};" : "=l"(r) : "r"(ahi), "r"(blo));
    return r;
}

// Fused Conv3d(3->16,k=3,valid) + bias + min over D + softmax over C.
// One thread = (n, h', w-PAIR, channel-group of 8). f32x2 packs TWO ADJACENT
// W PIXELS (not channels): x loads are natural LDG.64, weights are
// pre-replicated {w,w} in smem. kh unrolled (R8 win), ci rolled, TD=4.
__global__ __launch_bounds__(64, 8)
void fused_conv_min_softmax(const float* __restrict__ x,
                            const float* __restrict__ wgt,
                            const float* __restrict__ bias,
                            float* __restrict__ out)
{
    // wspd[pos(81)][c(16)] = {w,w} replicated pairs.
    __shared__ ull    wspd[81 * 16];
    __shared__ float  bsh[16];
    __shared__ float2 sred[2][32];

    const int tid = threadIdx.x;
    for (int i = tid; i < 81 * 16; i += 64) {
        const int c   = i & 15;
        const int pos = i >> 4;
        wspd[i] = rep2(wgt[c * 81 + pos]);
    }
    if (tid < 16) bsh[tid] = bias[tid];
    __syncthreads();

    const int lane = tid & 31;          // w-pair index
    const int cg   = tid >> 5;          // channel group 0/1
    const bool active = (lane < 31);    // 31 pairs cover w 0..61
    const int q  = active ? lane : 30;
    const int w0 = q << 1;              // even -> 8B-aligned pair loads

    const int h = blockIdx.x;           // 0..61
    const int n = blockIdx.y;           // 0..15

    // mins per pixel (low/high of the pair) per channel
    float mv0[8], mv1[8];
#pragma unroll
    for (int c = 0; c < 8; c++) { mv0[c] = 3.402823466e38f; mv1[c] = 3.402823466e38f; }

    // x layout [ci][d][y][w]: strides 262144 / 4096 / 64 floats
    const float* xbase = x + (size_t)n * (CIN * 262144) + h * 64 + w0;
    const ull* wcg = &wspd[cg * 8];

    // 16 depth tiles of 4: d0 = 0,4,...,56, then 58 (overlap; min idempotent)
#pragma unroll 1
    for (int t = 0; t < 16; t++) {
        const int d0 = (t < 15) ? (t << 2) : 58;

        ull acc[4][8];   // [depth][channel], each = {pixel0, pixel1}
#pragma unroll
        for (int d = 0; d < 4; d++)
#pragma unroll
            for (int c = 0; c < 8; c++) acc[d][c] = 0ull;

#pragma unroll 1
        for (int ci = 0; ci < CIN; ci++) {
            const float* cb = xbase + ci * 262144 + d0 * 4096;

            // kh UNROLLED: compile-time offsets, ptxas pipelines across bodies
#pragma unroll
            for (int kh = 0; kh < 3; kh++) {
                const float* rp0 = cb + kh * 64;

                // 6 depth-rows; per row: {x0,x1},{x2,x3} LDG.64 + mid pack
                ull xr[6][3];
#pragma unroll
                for (int r = 0; r < 6; r++) {
                    const float* rp = rp0 + r * 4096;
                    const ull a = *(const ull*)rp;        // {x0,x1}
                    const ull b = *(const ull*)(rp + 2);  // {x2,x3}
                    xr[r][0] = a;
                    xr[r][1] = mid2(a, b);                // {x1,x2}
                    xr[r][2] = b;
                }

#pragma unroll
                for (int kd = 0; kd < 3; kd++) {
#pragma unroll
                    for (int kw = 0; kw < 3; kw++) {
                        const int pos = ci * 27 + kd * 9 + kh * 3 + kw;
                        const ulonglong2* w2 =
                            (const ulonglong2*)&wcg[pos * 16];
#pragma unroll
                        for (int c4 = 0; c4 < 4; c4++) {
                            const ulonglong2 wp = w2[c4];
#pragma unroll
                            for (int d = 0; d < 4; d++) {
                                fma2(acc[d][2 * c4],     xr[kd + d][kw], wp.x);
                                fma2(acc[d][2 * c4 + 1], xr[kd + d][kw], wp.y);
                            }
                        }
                    }
                }
            }
        }

#pragma unroll
        for (int d = 0; d < 4; d++)
#pragma unroll
            for (int c = 0; c < 8; c++) {
                const float2 v = unpk(acc[d][c]);
                mv0[c] = fminf(mv0[c], v.x);
                mv1[c] = fminf(mv1[c], v.y);
            }
    }

    // bias + softmax over 16 channels per pixel, split across 2 threads (cg)
    float v0[8], v1[8];
    float2 mx = make_float2(-3.402823466e38f, -3.402823466e38f);
#pragma unroll
    for (int c = 0; c < 8; c++) {
        v0[c] = mv0[c] + bsh[cg * 8 + c];
        v1[c] = mv1[c] + bsh[cg * 8 + c];
        mx.x = fmaxf(mx.x, v0[c]);
        mx.y = fmaxf(mx.y, v1[c]);
    }
    sred[cg][lane] = mx;
    __syncthreads();
    {
        const float2 a = sred[0][lane];
        const float2 b = sred[1][lane];
        mx.x = fmaxf(a.x, b.x);
        mx.y = fmaxf(a.y, b.y);
    }
    __syncthreads();

    float2 s = make_float2(0.f, 0.f);
#pragma unroll
    for (int c = 0; c < 8; c++) {
        v0[c] = __expf(v0[c] - mx.x);
        v1[c] = __expf(v1[c] - mx.y);
        s.x += v0[c];
        s.y += v1[c];
    }
    sred[cg][lane] = s;
    __syncthreads();
    float2 inv;
    {
        const float2 a = sred[0][lane];
        const float2 b = sred[1][lane];
        inv.x = 1.0f / (a.x + b.x);
        inv.y = 1.0f / (a.y + b.y);
    }

    if (active) {
        const int hw = h * OW + w0;  // even -> 8B-aligned float2 store
#pragma unroll
        for (int c = 0; c < 8; c++) {
            float2 o;
            o.x = v0[c] * inv.x;
            o.y = v1[c] * inv.y;
            *(float2*)&out[(size_t)(n * COUT + cg * 8 + c) * (OH * OW) + hw] = o;
        }
    }
}

extern "C" void kernel_launch(void* const* d_in, const int* in_sizes, int n_in,
                              void* d_out, int out_size)
{
    const float* x    = (const float*)d_in[0];  // [16,3,64,64,64]
    const float* wgt  = (const float*)d_in[1];  // [16,3,3,3,3]
    const float* bias = (const float*)d_in[2];  // [16]
    float* out = (float*)d_out;                 // [16,16,62,62]

    dim3 grid(OH, 16);   // (h', n)
    dim3 block(64);      // 32 w-pair lanes x 2 channel groups
    fused_conv_min_softmax<<<grid, block>>>(x, wgt, bias, out);
}

// round 10
// speedup vs baseline: 1.5637x; 1.5637x over previous
#include <cuda_runtime.h>

#define CIN  3
#define COUT 16
#define OD   62
#define OH   62
#define OW   62

typedef unsigned long long ull;

__device__ __forceinline__ void fma2(ull& acc, ull x, ull w) {
    asm("fma.rn.f32x2 %0, %1, %2, %0;" : "+l"(acc) : "l"(x), "l"(w));
}
__device__ __forceinline__ ull rep2(float a) {
    ull r;
    asm("mov.b64 %0, {%1, %1};" : "=l"(r) : "f"(a));
    return r;
}
__device__ __forceinline__ float2 unpk(ull v) {
    float2 r;
    asm("mov.b64 {%0, %1}, %2;" : "=f"(r.x), "=f"(r.y) : "l"(v));
    return r;
}

// Fused Conv3d(3->16,k=3,valid) + bias + min over D + softmax over C.
// One thread = (n, h', w', channel-group of 8). f32x2 accumulators over
// channel pairs, depth tile of 4, kh unrolled (R8). NEW vs R8: weight
// fetch per tap = 2x LDS.128 (was 4x LDS.64) -> FMA2 instruction share
// 0.667 -> 0.727 with zero additional live registers.
__global__ __launch_bounds__(128, 4)
void fused_conv_min_softmax(const float* __restrict__ x,
                            const float* __restrict__ wgt,
                            const float* __restrict__ bias,
                            float* __restrict__ out)
{
    // Weights transposed to [pos(81)][c(16)]; adjacent channels = f32x2 pairs.
    __shared__ __align__(16) ull wsp[81 * 8];
    __shared__ float bsh[16];
    __shared__ float sred[2][64];
    float* wsf = (float*)wsp;

    const int tid = threadIdx.x;
    for (int i = tid; i < 81 * 16; i += 128) {
        const int c   = i & 15;
        const int pos = i >> 4;
        wsf[i] = wgt[c * 81 + pos];
    }
    if (tid < 16) bsh[tid] = bias[tid];
    __syncthreads();

    const int cg = tid >> 6;          // channel group 0/1 (channels cg*8..+7)
    const int wl = tid & 63;          // lane-w
    const bool active = (wl < OW);
    const int w = active ? wl : 0;    // clamp for safe addressing

    const int h = blockIdx.x;         // 0..61
    const int n = blockIdx.y;         // 0..15

    float mval[8];
#pragma unroll
    for (int c = 0; c < 8; c++) mval[c] = 3.402823466e38f;

    // x layout [ci][d][y][w]: strides 262144 / 4096 / 64
    const float* xbase = x + (size_t)n * (CIN * 262144) + h * 64 + w;
    const ull* wcg = &wsp[cg * 4];

    // 16 depth tiles of 4: d0 = 0,4,...,56, then 58 (overlap; min idempotent)
#pragma unroll 1
    for (int t = 0; t < 16; t++) {
        const int d0 = (t < 15) ? (t << 2) : 58;

        ull acc[4][4];
#pragma unroll
        for (int d = 0; d < 4; d++)
#pragma unroll
            for (int pr = 0; pr < 4; pr++) acc[d][pr] = 0ull;

#pragma unroll 1
        for (int ci = 0; ci < CIN; ci++) {
            const float* cb = xbase + ci * 262144 + d0 * 4096;

            // kh UNROLLED: 3 bodies with compile-time kh*64 offsets.
#pragma unroll
            for (int kh = 0; kh < 3; kh++) {
                const float* rp0 = cb + kh * 64;

                // 6 input-depth rows cover kd(0..2) x depth-tile(0..3)
                ull xr[6][3];
#pragma unroll
                for (int r = 0; r < 6; r++) {
                    const float* rp = rp0 + r * 4096;
                    xr[r][0] = rep2(rp[0]);
                    xr[r][1] = rep2(rp[1]);
                    xr[r][2] = rep2(rp[2]);
                }

#pragma unroll
                for (int kd = 0; kd < 3; kd++) {
#pragma unroll
                    for (int kw = 0; kw < 3; kw++) {
                        const int pos = ci * 27 + kd * 9 + kh * 3 + kw;
                        // 2x LDS.128: 4 weight pairs per tap (uniform addr -> broadcast)
                        const ulonglong2* w2 =
                            (const ulonglong2*)&wcg[pos * 8];
                        const ulonglong2 wa = w2[0];
                        const ulonglong2 wb = w2[1];
                        const ull wv0 = wa.x, wv1 = wa.y;
                        const ull wv2 = wb.x, wv3 = wb.y;
#pragma unroll
                        for (int d = 0; d < 4; d++) {
                            const ull xv = xr[kd + d][kw];
                            fma2(acc[d][0], xv, wv0);
                            fma2(acc[d][1], xv, wv1);
                            fma2(acc[d][2], xv, wv2);
                            fma2(acc[d][3], xv, wv3);
                        }
                    }
                }
            }
        }

#pragma unroll
        for (int d = 0; d < 4; d++)
#pragma unroll
            for (int pr = 0; pr < 4; pr++) {
                const float2 v = unpk(acc[d][pr]);
                mval[2 * pr]     = fminf(mval[2 * pr],     v.x);
                mval[2 * pr + 1] = fminf(mval[2 * pr + 1], v.y);
            }
    }

    // bias + softmax over 16 channels, split across 2 threads (cg 0/1)
    float v[8];
    float mx = -3.402823466e38f;
#pragma unroll
    for (int c = 0; c < 8; c++) {
        v[c] = mval[c] + bsh[cg * 8 + c];
        mx = fmaxf(mx, v[c]);
    }
    sred[cg][wl] = mx;
    __syncthreads();
    mx = fmaxf(sred[0][wl], sred[1][wl]);
    __syncthreads();

    float s = 0.f;
#pragma unroll
    for (int c = 0; c < 8; c++) {
        v[c] = __expf(v[c] - mx);
        s += v[c];
    }
    sred[cg][wl] = s;
    __syncthreads();
    const float inv = 1.0f / (sred[0][wl] + sred[1][wl]);

    if (active) {
        const int hw = h * OW + w;
#pragma unroll
        for (int c = 0; c < 8; c++) {
            out[(size_t)(n * COUT + cg * 8 + c) * (OH * OW) + hw] = v[c] * inv;
        }
    }
}

extern "C" void kernel_launch(void* const* d_in, const int* in_sizes, int n_in,
                              void* d_out, int out_size)
{
    const float* x    = (const float*)d_in[0];  // [16,3,64,64,64]
    const float* wgt  = (const float*)d_in[1];  // [16,3,3,3,3]
    const float* bias = (const float*)d_in[2];  // [16]
    float* out = (float*)d_out;                 // [16,16,62,62]

    dim3 grid(OH, 16);   // (h', n)
    dim3 block(128);     // 64 w-lanes x 2 channel groups
    fused_conv_min_softmax<<<grid, block>>>(x, wgt, bias, out);
}